// round 15
// baseline (speedup 1.0000x reference)
#include <cuda_runtime.h>
#include <cuda_fp16.h>
#include <math.h>

#define N_IMG 16
#define HH 512
#define WW 512
#define HW (HH*WW)
#define NPIX (N_IMG*HW)
#define GRIDN 8
#define TH 64
#define TW 64
#define AREA (TH*TW)
#define NBINS 256
#define NTILES (GRIDN*GRIDN)
#define LAB_BLOCKS8 (NPIX/8/256)         // 2048 (k_lab, 8 px/thread)
#define LAB_BPI8 (LAB_BLOCKS8/N_IMG)     // 128
#define OUT_BLOCKS (NPIX/4/256)          // 4096 (k_out, 4 px/thread)
#define OUT_BPI (OUT_BLOCKS/N_IMG)       // 256
#define MINMAX_N LAB_BLOCKS8
#define QGRID 7
#define QPERIMG (QGRID*QGRID*NBINS)      // 12544

#define LAB_EPS (216.0f/24389.0f)
#define LAB_KAPPA (24389.0f/27.0f)

// ---------------- scratch ----------------
__device__ float   g_L[NPIX];
__device__ __half2 g_ab[NPIX];           // (a/500, -b/200) as half2
__device__ unsigned char g_lint[NPIX];
__device__ float g_blkmin[MINMAX_N];
__device__ float g_blkmax[MINMAX_N];
__device__ int    g_tilehist[N_IMG*NTILES*NBINS];
__device__ float  g_tilelut [N_IMG*NTILES*NBINS];
__device__ float2 g_eqlut2  [N_IMG*NBINS];      // (fy0, finv(fy0))
__device__ uint4  g_quadE   [N_IMG*QPERIMG];    // {quadPacked, fy0, Y0, 0}
__device__ int4   g_cxlut4  [WW/4];             // per 4-px group: (wx0, x0*NBINS, dwx, 0)
__device__ int2   g_cylut   [HH];

// ---------------- MUFU primitives ----------------
__device__ __forceinline__ float ex2f(float x){ float r; asm("ex2.approx.f32 %0, %1;" : "=f"(r) : "f"(x)); return r; }
__device__ __forceinline__ float lg2f(float x){ float r; asm("lg2.approx.f32 %0, %1;" : "=f"(r) : "f"(x)); return r; }

// ---------------- scalar helpers ----------------
__device__ __forceinline__ float srgb2lin(float c) {
    float lin = c * (1.0f/12.92f);
    float p = ex2f(2.4f * lg2f(fmaf(c, 1.0f/1.055f, 0.055f/1.055f)));
    return (c <= 0.04045f) ? lin : p;
}
__device__ __forceinline__ float labf(float x) {
    float lin = fmaf(x, LAB_KAPPA/116.0f, 16.0f/116.0f);
    float p = ex2f(lg2f(x) * (1.0f/3.0f));
    return (x > LAB_EPS) ? p : lin;
}
__device__ __forceinline__ float finv(float f) {
    float f3 = f * f * f;
    float lin = fmaf(f, 116.0f/LAB_KAPPA, -16.0f/LAB_KAPPA);
    return (f3 > LAB_EPS) ? f3 : lin;
}
__device__ __forceinline__ float srgb255s(float c) {
    float lin = c * (12.92f * 255.0f);
    float p = ex2f(fmaf(lg2f(c), 1.0f/2.4f, 8.0715942f)) - 14.025f;
    float r = (c <= 0.0031308f) ? lin : p;
    return fminf(fmaxf(r, 0.0f), 255.0f);
}
// exact uchar->float via PRMT + magic subtract
__device__ __forceinline__ float ub2f(unsigned int q, int sel) {
    return __uint_as_float(__byte_perm(q, 0x4B000000u, sel)) - 8388608.0f;
}

__device__ __forceinline__ float inclusive_scan_256(float v, float* ws8) {
    int lane = threadIdx.x & 31, warp = threadIdx.x >> 5;
    #pragma unroll
    for (int o = 1; o < 32; o <<= 1) {
        float t = __shfl_up_sync(0xFFFFFFFFu, v, o);
        if (lane >= o) v += t;
    }
    if (lane == 31) ws8[warp] = v;
    __syncthreads();
    if (warp == 0 && lane < 8) {
        float s = ws8[lane];
        #pragma unroll
        for (int o = 1; o < 8; o <<= 1) {
            float t = __shfl_up_sync(0xFFu, s, o);
            if (lane >= o) s += t;
        }
        ws8[lane] = s;
    }
    __syncthreads();
    if (warp > 0) v += ws8[warp - 1];
    return v;
}

// ---------------- K1: RGB -> Lab (8 px/thread) + per-block min/max ----------------
__global__ void k_lab(const float* __restrict__ x) {
    int t  = blockIdx.x * blockDim.x + threadIdx.x;
    int p8 = t * 8;
    int n  = blockIdx.x / LAB_BPI8;
    int hw = p8 - n * HW;
    const float* img = x + (size_t)n * 3 * HW;
    float4 R0 = __ldcs((const float4*)(img + hw));
    float4 R1 = __ldcs((const float4*)(img + hw + 4));
    float4 G0 = __ldcs((const float4*)(img + HW + hw));
    float4 G1 = __ldcs((const float4*)(img + HW + hw + 4));
    float4 B0 = __ldcs((const float4*)(img + 2*HW + hw));
    float4 B1 = __ldcs((const float4*)(img + 2*HW + hw + 4));
    float Rf[8], Gf[8], Bf[8];
    *(float4*)(Rf) = R0; *(float4*)(Rf+4) = R1;
    *(float4*)(Gf) = G0; *(float4*)(Gf+4) = G1;
    *(float4*)(Bf) = B0; *(float4*)(Bf+4) = B1;

    float Lo[8];
    __half2 ab[8];
    float vmin =  1e30f, vmax = -1e30f;
    #pragma unroll
    for (int k = 0; k < 8; k++) {
        float lr = srgb2lin(Rf[k]);
        float lg = srgb2lin(Gf[k]);
        float lb = srgb2lin(Bf[k]);
        float X = 0.43395038f*lr;
        X = fmaf(0.37621015f, lg, X);
        X = fmaf(0.18984050f, lb, X);
        float Y = 0.21267290f*lr;
        Y = fmaf(0.71515220f, lg, Y);
        Y = fmaf(0.07217500f, lb, Y);
        float Z = 0.01775650f*lr;
        Z = fmaf(0.10946790f, lg, Z);
        Z = fmaf(0.87277544f, lb, Z);
        float fx = labf(X), fy = labf(Y), fz = labf(Z);
        float L = fmaf(fy, 116.0f, -16.0f);
        // store pre-scaled: (a/500, -b/200) = (fx - fy, fz - fy)... careful:
        // a/500 = fx - fy ; -b/200 = fz - fy
        ab[k] = __floats2half2_rn(fx - fy, fz - fy);
        Lo[k] = L;
        vmin = fminf(vmin, L); vmax = fmaxf(vmax, L);
    }
    *(float4*)(g_L + p8)     = *(float4*)Lo;
    *(float4*)(g_L + p8 + 4) = *(float4*)(Lo + 4);
    *(uint4*)(g_ab + p8)     = *(uint4*)ab;
    *(uint4*)(g_ab + p8 + 4) = *(uint4*)(ab + 4);

    #pragma unroll
    for (int o = 16; o > 0; o >>= 1) {
        vmin = fminf(vmin, __shfl_down_sync(0xFFFFFFFFu, vmin, o));
        vmax = fmaxf(vmax, __shfl_down_sync(0xFFFFFFFFu, vmax, o));
    }
    __shared__ float wmin[8], wmax[8];
    int lane = threadIdx.x & 31, warp = threadIdx.x >> 5;
    if (lane == 0) { wmin[warp] = vmin; wmax[warp] = vmax; }
    __syncthreads();
    if (threadIdx.x == 0) {
        float bmin = wmin[0], bmax = wmax[0];
        #pragma unroll
        for (int i = 1; i < 8; i++) {
            bmin = fminf(bmin, wmin[i]);
            bmax = fmaxf(bmax, wmax[i]);
        }
        g_blkmin[blockIdx.x] = bmin;
        g_blkmax[blockIdx.x] = bmax;
    }
}

// ---------------- K2: min/max finalize + quantize + tile hist + tile LUT ----------------
__global__ void k_quant_hist_lut() {
    int blk = blockIdx.x;
    int n = blk >> 6;
    int t = blk & 63;
    int ty = t >> 3, tx = t & 7;

    __shared__ int shw[8][NBINS];
    __shared__ float wmin[8], wmax[8];
    __shared__ float ws8[8];
    __shared__ float s_lmin, s_scale, s_totc;

    float vmin =  1e30f, vmax = -1e30f;
    if (threadIdx.x < LAB_BPI8) {
        vmin = g_blkmin[n * LAB_BPI8 + threadIdx.x];
        vmax = g_blkmax[n * LAB_BPI8 + threadIdx.x];
    }
    #pragma unroll
    for (int o = 16; o > 0; o >>= 1) {
        vmin = fminf(vmin, __shfl_down_sync(0xFFFFFFFFu, vmin, o));
        vmax = fmaxf(vmax, __shfl_down_sync(0xFFFFFFFFu, vmax, o));
    }
    int lane = threadIdx.x & 31, warp = threadIdx.x >> 5;
    if (lane == 0) { wmin[warp] = vmin; wmax[warp] = vmax; }
    #pragma unroll
    for (int w = 0; w < 8; w++) shw[w][threadIdx.x] = 0;
    __syncthreads();
    if (threadIdx.x == 0) {
        float bmin = wmin[0], bmax = wmax[0];
        #pragma unroll
        for (int i = 1; i < 4; i++) {
            bmin = fminf(bmin, wmin[i]);
            bmax = fmaxf(bmax, wmax[i]);
        }
        s_lmin = bmin;
        s_scale = 255.0f / (bmax - bmin + 1e-6f);
    }
    __syncthreads();

    float lmin = s_lmin, scale = s_scale;
    int* myh = shw[warp];
    int base = n * HW + (ty * TH) * WW + tx * TW;
    #pragma unroll
    for (int it = 0; it < 4; it++) {
        int i = threadIdx.x + it * 256;
        int row = i >> 4, c16 = i & 15;
        int p = base + row * WW + c16 * 4;
        float4 L4 = __ldlu((const float4*)(g_L + p));
        int v0 = min(max((int)rintf((L4.x - lmin) * scale), 0), 255);
        int v1 = min(max((int)rintf((L4.y - lmin) * scale), 0), 255);
        int v2 = min(max((int)rintf((L4.z - lmin) * scale), 0), 255);
        int v3 = min(max((int)rintf((L4.w - lmin) * scale), 0), 255);
        *(uchar4*)(g_lint + p) = make_uchar4((unsigned char)v0, (unsigned char)v1,
                                             (unsigned char)v2, (unsigned char)v3);
        atomicAdd(&myh[v0], 1);
        atomicAdd(&myh[v1], 1);
        atomicAdd(&myh[v2], 1);
        atomicAdd(&myh[v3], 1);
    }
    __syncthreads();

    int hist = 0;
    #pragma unroll
    for (int w = 0; w < 8; w++) hist += shw[w][threadIdx.x];
    g_tilehist[blk * NBINS + threadIdx.x] = hist;

    float clipped = fminf((float)hist, 32.0f);
    float cum = inclusive_scan_256(clipped, ws8);
    if (threadIdx.x == 255) s_totc = cum;
    __syncthreads();
    float excess = (float)AREA - s_totc;
    float val = cum + (float)(threadIdx.x + 1) * (excess * (1.0f/256.0f));
    g_tilelut[blk * NBINS + threadIdx.x] = rintf(val * (255.0f / (float)AREA));
}

// ---------------- K3a: equalize LUT + coordinate LUTs (16 blocks) ----------------
__global__ void k_eq() {
    __shared__ float ws8[8];
    int n = blockIdx.x;
    int t = threadIdx.x;
    int s = 0;
    #pragma unroll
    for (int tt = 0; tt < NTILES; tt++)
        s += g_tilehist[(n * NTILES + tt) * NBINS + t];
    float cum = inclusive_scan_256((float)s, ws8);
    float eq_l = rintf(cum * (255.0f / (float)HW));
    float fy0 = fmaf(eq_l, 100.0f/(255.0f*116.0f), 16.0f/116.0f);
    g_eqlut2[n * NBINS + t] = make_float2(fy0, finv(fy0));

    if (n == 0) {
        if (t < WW/4) {
            int w = t * 4;
            float cx0 = fminf(fmaxf(((float)w + 0.5f) * (1.0f/TW) - 0.5f, 0.0f), 7.0f);
            float cx1 = fminf(fmaxf(((float)w + 1.5f) * (1.0f/TW) - 0.5f, 0.0f), 7.0f);
            int x0 = min((int)cx0, GRIDN - 2);
            float wx0 = cx0 - (float)x0;
            float dwx = cx1 - cx0;            // exactly 0 or 1/64
            g_cxlut4[t] = make_int4(__float_as_int(wx0), x0 * NBINS,
                                    __float_as_int(dwx), 0);
        }
    } else if (n == 1) {
        #pragma unroll
        for (int h = t; h < HH; h += 256) {
            float cy = fminf(fmaxf(((float)h + 0.5f) * (1.0f/TH) - 0.5f, 0.0f), 7.0f);
            int y0 = min((int)cy, GRIDN - 2);
            g_cylut[h] = make_int2(__float_as_int(cy - (float)y0), y0 * (QGRID * NBINS));
        }
    }
}

// ---------------- K3b: combined quad+eq table (784 blocks) ----------------
__global__ void k_quadE() {
    int blk = blockIdx.x;
    int t = threadIdx.x;
    int n  = blk / (QGRID * QGRID);
    int r  = blk - n * (QGRID * QGRID);
    int y0 = r / QGRID;
    int x0 = r - y0 * QGRID;
    const float* lb = g_tilelut + ((n * GRIDN + y0) * GRIDN + x0) * NBINS + t;
    unsigned int v00 = (unsigned int)lb[0];
    unsigned int v01 = (unsigned int)lb[NBINS];
    unsigned int v10 = (unsigned int)lb[GRIDN * NBINS];
    unsigned int v11 = (unsigned int)lb[GRIDN * NBINS + NBINS];
    unsigned int quad = v00 | (v01 << 8) | (v10 << 16) | (v11 << 24);
    float2 eq = g_eqlut2[n * NBINS + t];
    g_quadE[blk * NBINS + t] = make_uint4(quad, __float_as_int(eq.x),
                                          __float_as_int(eq.y), 0u);
}

// ---------------- K4: reconstruct both outputs (single LDG.128 gather/px) ----------
__global__ void __launch_bounds__(256, 6) k_out(float* __restrict__ out) {
    int t  = blockIdx.x * blockDim.x + threadIdx.x;
    int p4 = t * 4;
    int n  = blockIdx.x / OUT_BPI;
    int hw = p4 - n * HW;
    int h = hw >> 9, w0 = hw & 511;

    unsigned int lraw = __ldlu((const unsigned int*)(g_lint + p4));
    uchar4 v4 = *(uchar4*)&lraw;
    uint4 abraw = __ldlu((const uint4*)(g_ab + p4));

    int2 cye = g_cylut[h];
    float wy = __int_as_float(cye.x);
    int4 cxe = g_cxlut4[w0 >> 2];
    float wx0 = __int_as_float(cxe.x);
    float dwx = __int_as_float(cxe.z);
    const uint4* qrow = g_quadE + n * QPERIMG + cye.y + cxe.y;

    float a500[4], nb200[4];
    #pragma unroll
    for (int k = 0; k < 4; k++) {
        unsigned int abu = (k==0)?abraw.x:(k==1)?abraw.y:(k==2)?abraw.z:abraw.w;
        float2 abf = __half22float2(*(__half2*)&abu);
        a500[k]  = abf.x;           // a/500 pre-scaled
        nb200[k] = abf.y;           // -b/200 pre-scaled
    }

    size_t base0 = (size_t)n * 3 * HW + hw;
    size_t base1 = (size_t)NPIX * 3 + base0;

    float cl_l[4];
    // ---- phase 1: gather once, equalize output, stash clahe L ----
    {
        float Ro[4], Go[4], Bo[4];
        #pragma unroll
        for (int k = 0; k < 4; k++) {
            int v = (k==0)?v4.x:(k==1)?v4.y:(k==2)?v4.z:v4.w;
            uint4 e = qrow[v];                     // {quad, fy0, Y0, 0}
            float fy0 = __int_as_float(e.y);
            float Y   = __int_as_float(e.z);
            float X = finv(fy0 + a500[k]);
            float Z = finv(fy0 + nb200[k]);
            Ro[k] = srgb255s( 3.0799546f*X - 1.5371385f*Y - 0.5428164f*Z);
            Go[k] = srgb255s(-0.9212582f*X + 1.8760108f*Y + 0.0452474f*Z);
            Bo[k] = srgb255s( 0.0528874f*X - 0.2040259f*Y + 1.1511382f*Z);

            unsigned int q = e.x;
            float wx = fmaf((float)k, dwx, wx0);
            float v00 = ub2f(q, 0x7440);
            float v01 = ub2f(q, 0x7441);
            float v10 = ub2f(q, 0x7442);
            float v11 = ub2f(q, 0x7443);
            float top = fmaf(wx, v01 - v00, v00);
            float bot = fmaf(wx, v11 - v10, v10);
            cl_l[k] = fmaf(wy, bot - top, top);
        }
        __stcs((float4*)(out + base0),        *(float4*)Ro);
        __stcs((float4*)(out + base0 + HW),   *(float4*)Go);
        __stcs((float4*)(out + base0 + 2*HW), *(float4*)Bo);
    }

    // ---- phase 2: clahe output ----
    {
        float Ro[4], Go[4], Bo[4];
        #pragma unroll
        for (int k = 0; k < 4; k++) {
            float fy1 = fmaf(cl_l[k], 100.0f/(255.0f*116.0f), 16.0f/116.0f);
            float X = finv(fy1 + a500[k]);
            float Z = finv(fy1 + nb200[k]);
            float Y = finv(fy1);
            Ro[k] = srgb255s( 3.0799546f*X - 1.5371385f*Y - 0.5428164f*Z);
            Go[k] = srgb255s(-0.9212582f*X + 1.8760108f*Y + 0.0452474f*Z);
            Bo[k] = srgb255s( 0.0528874f*X - 0.2040259f*Y + 1.1511382f*Z);
        }
        __stcs((float4*)(out + base1),        *(float4*)Ro);
        __stcs((float4*)(out + base1 + HW),   *(float4*)Go);
        __stcs((float4*)(out + base1 + 2*HW), *(float4*)Bo);
    }
}

// ---------------- launch ----------------
extern "C" void kernel_launch(void* const* d_in, const int* in_sizes, int n_in,
                              void* d_out, int out_size) {
    const float* x = (const float*)d_in[0];
    float* out = (float*)d_out;
    (void)in_sizes; (void)n_in; (void)out_size;

    k_lab<<<LAB_BLOCKS8, 256>>>(x);
    k_quant_hist_lut<<<N_IMG * NTILES, 256>>>();
    k_eq<<<N_IMG, NBINS>>>();
    k_quadE<<<N_IMG * QGRID * QGRID, NBINS>>>();
    k_out<<<OUT_BLOCKS, 256>>>(out);
}

// round 16
// speedup vs baseline: 1.0468x; 1.0468x over previous
#include <cuda_runtime.h>
#include <cuda_fp16.h>
#include <math.h>

#define N_IMG 16
#define HH 512
#define WW 512
#define HW (HH*WW)
#define NPIX (N_IMG*HW)
#define GRIDN 8
#define TH 64
#define TW 64
#define AREA (TH*TW)
#define NBINS 256
#define NTILES (GRIDN*GRIDN)
#define LAB_BLOCKS8 (NPIX/8/256)         // 2048 (k_lab, 8 px/thread)
#define LAB_BPI8 (LAB_BLOCKS8/N_IMG)     // 128
#define OUT_BLOCKS (NPIX/4/256)          // 4096 (k_out, 4 px/thread)
#define OUT_BPI (OUT_BLOCKS/N_IMG)       // 256
#define MINMAX_N LAB_BLOCKS8
#define QGRID 7
#define QPERIMG (QGRID*QGRID*NBINS)

#define LAB_EPS (216.0f/24389.0f)
#define LAB_KAPPA (24389.0f/27.0f)

// ---------------- scratch ----------------
__device__ float   g_L[NPIX];
__device__ __half2 g_ab[NPIX];           // pre-scaled (a/500, -b/200)
__device__ unsigned char g_lint[NPIX];
__device__ float g_blkmin[MINMAX_N];
__device__ float g_blkmax[MINMAX_N];
__device__ int    g_tilehist[N_IMG*NTILES*NBINS];
__device__ float  g_tilelut [N_IMG*NTILES*NBINS];
__device__ float2 g_eqlut2  [N_IMG*NBINS];      // (fy0, finv(fy0))
__device__ unsigned int g_quadU[N_IMG*QPERIMG]; // packed uchar corners
__device__ int4   g_cxlut4  [WW/4];             // per 4-px group: (wx0, x0*NBINS, dwx, 0)
__device__ int2   g_cylut   [HH];

// ---------------- MUFU primitives ----------------
__device__ __forceinline__ float ex2f(float x){ float r; asm("ex2.approx.f32 %0, %1;" : "=f"(r) : "f"(x)); return r; }
__device__ __forceinline__ float lg2f(float x){ float r; asm("lg2.approx.f32 %0, %1;" : "=f"(r) : "f"(x)); return r; }

// ---------------- scalar helpers ----------------
__device__ __forceinline__ float srgb2lin(float c) {
    float lin = c * (1.0f/12.92f);
    float p = ex2f(2.4f * lg2f(fmaf(c, 1.0f/1.055f, 0.055f/1.055f)));
    return (c <= 0.04045f) ? lin : p;
}
__device__ __forceinline__ float labf(float x) {
    float lin = fmaf(x, LAB_KAPPA/116.0f, 16.0f/116.0f);
    float p = ex2f(lg2f(x) * (1.0f/3.0f));
    return (x > LAB_EPS) ? p : lin;
}
__device__ __forceinline__ float finv(float f) {
    float f3 = f * f * f;
    float lin = fmaf(f, 116.0f/LAB_KAPPA, -16.0f/LAB_KAPPA);
    return (f3 > LAB_EPS) ? f3 : lin;
}
__device__ __forceinline__ float srgb255s(float c) {
    float lin = c * (12.92f * 255.0f);
    float p = ex2f(fmaf(lg2f(c), 1.0f/2.4f, 8.0715942f)) - 14.025f;
    float r = (c <= 0.0031308f) ? lin : p;
    return fminf(fmaxf(r, 0.0f), 255.0f);
}
// exact uchar->float via PRMT + magic subtract
__device__ __forceinline__ float ub2f(unsigned int q, int sel) {
    return __uint_as_float(__byte_perm(q, 0x4B000000u, sel)) - 8388608.0f;
}

__device__ __forceinline__ float inclusive_scan_256(float v, float* ws8) {
    int lane = threadIdx.x & 31, warp = threadIdx.x >> 5;
    #pragma unroll
    for (int o = 1; o < 32; o <<= 1) {
        float t = __shfl_up_sync(0xFFFFFFFFu, v, o);
        if (lane >= o) v += t;
    }
    if (lane == 31) ws8[warp] = v;
    __syncthreads();
    if (warp == 0 && lane < 8) {
        float s = ws8[lane];
        #pragma unroll
        for (int o = 1; o < 8; o <<= 1) {
            float t = __shfl_up_sync(0xFFu, s, o);
            if (lane >= o) s += t;
        }
        ws8[lane] = s;
    }
    __syncthreads();
    if (warp > 0) v += ws8[warp - 1];
    return v;
}

// ---------------- K1: RGB -> Lab (8 px/thread) + per-block min/max ----------------
__global__ void k_lab(const float* __restrict__ x) {
    int t  = blockIdx.x * blockDim.x + threadIdx.x;
    int p8 = t * 8;
    int n  = blockIdx.x / LAB_BPI8;
    int hw = p8 - n * HW;
    const float* img = x + (size_t)n * 3 * HW;
    float4 R0 = __ldcs((const float4*)(img + hw));
    float4 R1 = __ldcs((const float4*)(img + hw + 4));
    float4 G0 = __ldcs((const float4*)(img + HW + hw));
    float4 G1 = __ldcs((const float4*)(img + HW + hw + 4));
    float4 B0 = __ldcs((const float4*)(img + 2*HW + hw));
    float4 B1 = __ldcs((const float4*)(img + 2*HW + hw + 4));
    float Rf[8], Gf[8], Bf[8];
    *(float4*)(Rf) = R0; *(float4*)(Rf+4) = R1;
    *(float4*)(Gf) = G0; *(float4*)(Gf+4) = G1;
    *(float4*)(Bf) = B0; *(float4*)(Bf+4) = B1;

    float Lo[8];
    __half2 ab[8];
    float vmin =  1e30f, vmax = -1e30f;
    #pragma unroll
    for (int k = 0; k < 8; k++) {
        float lr = srgb2lin(Rf[k]);
        float lg = srgb2lin(Gf[k]);
        float lb = srgb2lin(Bf[k]);
        float X = 0.43395038f*lr;
        X = fmaf(0.37621015f, lg, X);
        X = fmaf(0.18984050f, lb, X);
        float Y = 0.21267290f*lr;
        Y = fmaf(0.71515220f, lg, Y);
        Y = fmaf(0.07217500f, lb, Y);
        float Z = 0.01775650f*lr;
        Z = fmaf(0.10946790f, lg, Z);
        Z = fmaf(0.87277544f, lb, Z);
        float fx = labf(X), fy = labf(Y), fz = labf(Z);
        float L = fmaf(fy, 116.0f, -16.0f);
        // pre-scaled chroma: a/500 = fx - fy ; -b/200 = fz - fy
        ab[k] = __floats2half2_rn(fx - fy, fz - fy);
        Lo[k] = L;
        vmin = fminf(vmin, L); vmax = fmaxf(vmax, L);
    }
    *(float4*)(g_L + p8)     = *(float4*)Lo;
    *(float4*)(g_L + p8 + 4) = *(float4*)(Lo + 4);
    *(uint4*)(g_ab + p8)     = *(uint4*)ab;
    *(uint4*)(g_ab + p8 + 4) = *(uint4*)(ab + 4);

    #pragma unroll
    for (int o = 16; o > 0; o >>= 1) {
        vmin = fminf(vmin, __shfl_down_sync(0xFFFFFFFFu, vmin, o));
        vmax = fmaxf(vmax, __shfl_down_sync(0xFFFFFFFFu, vmax, o));
    }
    __shared__ float wmin[8], wmax[8];
    int lane = threadIdx.x & 31, warp = threadIdx.x >> 5;
    if (lane == 0) { wmin[warp] = vmin; wmax[warp] = vmax; }
    __syncthreads();
    if (threadIdx.x == 0) {
        float bmin = wmin[0], bmax = wmax[0];
        #pragma unroll
        for (int i = 1; i < 8; i++) {
            bmin = fminf(bmin, wmin[i]);
            bmax = fmaxf(bmax, wmax[i]);
        }
        g_blkmin[blockIdx.x] = bmin;
        g_blkmax[blockIdx.x] = bmax;
    }
}

// ---------------- K2: min/max finalize + quantize + tile hist + tile LUT ----------------
__global__ void k_quant_hist_lut() {
    int blk = blockIdx.x;
    int n = blk >> 6;
    int t = blk & 63;
    int ty = t >> 3, tx = t & 7;

    __shared__ int shw[8][NBINS];
    __shared__ float wmin[8], wmax[8];
    __shared__ float ws8[8];
    __shared__ float s_lmin, s_scale, s_totc;

    float vmin =  1e30f, vmax = -1e30f;
    if (threadIdx.x < LAB_BPI8) {
        vmin = g_blkmin[n * LAB_BPI8 + threadIdx.x];
        vmax = g_blkmax[n * LAB_BPI8 + threadIdx.x];
    }
    #pragma unroll
    for (int o = 16; o > 0; o >>= 1) {
        vmin = fminf(vmin, __shfl_down_sync(0xFFFFFFFFu, vmin, o));
        vmax = fmaxf(vmax, __shfl_down_sync(0xFFFFFFFFu, vmax, o));
    }
    int lane = threadIdx.x & 31, warp = threadIdx.x >> 5;
    if (lane == 0) { wmin[warp] = vmin; wmax[warp] = vmax; }
    #pragma unroll
    for (int w = 0; w < 8; w++) shw[w][threadIdx.x] = 0;
    __syncthreads();
    if (threadIdx.x == 0) {
        float bmin = wmin[0], bmax = wmax[0];
        #pragma unroll
        for (int i = 1; i < 4; i++) {
            bmin = fminf(bmin, wmin[i]);
            bmax = fmaxf(bmax, wmax[i]);
        }
        s_lmin = bmin;
        s_scale = 255.0f / (bmax - bmin + 1e-6f);
    }
    __syncthreads();

    float lmin = s_lmin, scale = s_scale;
    int* myh = shw[warp];
    int base = n * HW + (ty * TH) * WW + tx * TW;
    #pragma unroll
    for (int it = 0; it < 4; it++) {
        int i = threadIdx.x + it * 256;
        int row = i >> 4, c16 = i & 15;
        int p = base + row * WW + c16 * 4;
        float4 L4 = __ldlu((const float4*)(g_L + p));
        int v0 = min(max((int)rintf((L4.x - lmin) * scale), 0), 255);
        int v1 = min(max((int)rintf((L4.y - lmin) * scale), 0), 255);
        int v2 = min(max((int)rintf((L4.z - lmin) * scale), 0), 255);
        int v3 = min(max((int)rintf((L4.w - lmin) * scale), 0), 255);
        *(uchar4*)(g_lint + p) = make_uchar4((unsigned char)v0, (unsigned char)v1,
                                             (unsigned char)v2, (unsigned char)v3);
        atomicAdd(&myh[v0], 1);
        atomicAdd(&myh[v1], 1);
        atomicAdd(&myh[v2], 1);
        atomicAdd(&myh[v3], 1);
    }
    __syncthreads();

    int hist = 0;
    #pragma unroll
    for (int w = 0; w < 8; w++) hist += shw[w][threadIdx.x];
    g_tilehist[blk * NBINS + threadIdx.x] = hist;

    float clipped = fminf((float)hist, 32.0f);
    float cum = inclusive_scan_256(clipped, ws8);
    if (threadIdx.x == 255) s_totc = cum;
    __syncthreads();
    float excess = (float)AREA - s_totc;
    float val = cum + (float)(threadIdx.x + 1) * (excess * (1.0f/256.0f));
    g_tilelut[blk * NBINS + threadIdx.x] = rintf(val * (255.0f / (float)AREA));
}

// ---------------- K3: packed quad table + equalize LUT + coordinate LUTs ----------------
__global__ void k_luts2() {
    int blk = blockIdx.x;
    int t = threadIdx.x;
    if (blk < N_IMG * QGRID * QGRID) {
        int n  = blk / (QGRID * QGRID);
        int r  = blk - n * (QGRID * QGRID);
        int y0 = r / QGRID;
        int x0 = r - y0 * QGRID;
        const float* lb = g_tilelut + ((n * GRIDN + y0) * GRIDN + x0) * NBINS + t;
        unsigned int v00 = (unsigned int)lb[0];
        unsigned int v01 = (unsigned int)lb[NBINS];
        unsigned int v10 = (unsigned int)lb[GRIDN * NBINS];
        unsigned int v11 = (unsigned int)lb[GRIDN * NBINS + NBINS];
        g_quadU[blk * NBINS + t] = v00 | (v01 << 8) | (v10 << 16) | (v11 << 24);
    } else {
        __shared__ float ws8[8];
        int n = blk - N_IMG * QGRID * QGRID;
        int s = 0;
        #pragma unroll
        for (int tt = 0; tt < NTILES; tt++)
            s += g_tilehist[(n * NTILES + tt) * NBINS + t];
        float cum = inclusive_scan_256((float)s, ws8);
        float eq_l = rintf(cum * (255.0f / (float)HW));
        float fy0 = fmaf(eq_l, 100.0f/(255.0f*116.0f), 16.0f/116.0f);
        g_eqlut2[n * NBINS + t] = make_float2(fy0, finv(fy0));

        if (n == 0) {
            if (t < WW/4) {
                int w = t * 4;
                float cx0 = fminf(fmaxf(((float)w + 0.5f) * (1.0f/TW) - 0.5f, 0.0f), 7.0f);
                float cx1 = fminf(fmaxf(((float)w + 1.5f) * (1.0f/TW) - 0.5f, 0.0f), 7.0f);
                int x0 = min((int)cx0, GRIDN - 2);
                float wx0 = cx0 - (float)x0;
                float dwx = cx1 - cx0;            // exactly 0 or 1/64
                g_cxlut4[t] = make_int4(__float_as_int(wx0), x0 * NBINS,
                                        __float_as_int(dwx), 0);
            }
        } else if (n == 1) {
            #pragma unroll
            for (int h = t; h < HH; h += 256) {
                float cy = fminf(fmaxf(((float)h + 0.5f) * (1.0f/TH) - 0.5f, 0.0f), 7.0f);
                int y0 = min((int)cy, GRIDN - 2);
                g_cylut[h] = make_int2(__float_as_int(cy - (float)y0), y0 * (QGRID * NBINS));
            }
        }
    }
}

// ---------------- K4: reconstruct both outputs (4 px/thread, group-cx LUT) ----------
__global__ void __launch_bounds__(256, 6) k_out(float* __restrict__ out) {
    int t  = blockIdx.x * blockDim.x + threadIdx.x;
    int p4 = t * 4;
    int n  = blockIdx.x / OUT_BPI;
    int hw = p4 - n * HW;
    int h = hw >> 9, w0 = hw & 511;

    unsigned int lraw = __ldlu((const unsigned int*)(g_lint + p4));
    uchar4 v4 = *(uchar4*)&lraw;
    uint4 abraw = __ldlu((const uint4*)(g_ab + p4));

    const float2* eqn = g_eqlut2 + n * NBINS;

    float a500[4], nb200[4];
    #pragma unroll
    for (int k = 0; k < 4; k++) {
        unsigned int abu = (k==0)?abraw.x:(k==1)?abraw.y:(k==2)?abraw.z:abraw.w;
        float2 abf = __half22float2(*(__half2*)&abu);
        a500[k]  = abf.x;            // a/500 pre-scaled
        nb200[k] = abf.y;            // -b/200 pre-scaled
    }

    size_t base0 = (size_t)n * 3 * HW + hw;
    size_t base1 = (size_t)NPIX * 3 + base0;

    // ---- phase 1: equalize output ----
    {
        float Ro[4], Go[4], Bo[4];
        #pragma unroll
        for (int k = 0; k < 4; k++) {
            int v = (k==0)?v4.x:(k==1)?v4.y:(k==2)?v4.z:v4.w;
            float2 eqv = eqn[v];                  // (fy0, finv(fy0))
            float X = finv(eqv.x + a500[k]);
            float Z = finv(eqv.x + nb200[k]);
            float Y = eqv.y;
            Ro[k] = srgb255s( 3.0799546f*X - 1.5371385f*Y - 0.5428164f*Z);
            Go[k] = srgb255s(-0.9212582f*X + 1.8760108f*Y + 0.0452474f*Z);
            Bo[k] = srgb255s( 0.0528874f*X - 0.2040259f*Y + 1.1511382f*Z);
        }
        __stcs((float4*)(out + base0),        *(float4*)Ro);
        __stcs((float4*)(out + base0 + HW),   *(float4*)Go);
        __stcs((float4*)(out + base0 + 2*HW), *(float4*)Bo);
    }

    // ---- phase 2: clahe output ----
    {
        int2 cye = g_cylut[h];
        float wy = __int_as_float(cye.x);
        int4 cxe = g_cxlut4[w0 >> 2];             // one load per 4-px group
        float wx0 = __int_as_float(cxe.x);
        float dwx = __int_as_float(cxe.z);
        const unsigned int* qrow = g_quadU + n * QPERIMG + cye.y + cxe.y;

        float Ro[4], Go[4], Bo[4];
        #pragma unroll
        for (int k = 0; k < 4; k++) {
            int v = (k==0)?v4.x:(k==1)?v4.y:(k==2)?v4.z:v4.w;
            float wx = fmaf((float)k, dwx, wx0);
            unsigned int q = qrow[v];
            float v00 = ub2f(q, 0x7440);
            float v01 = ub2f(q, 0x7441);
            float v10 = ub2f(q, 0x7442);
            float v11 = ub2f(q, 0x7443);
            float top = fmaf(wx, v01 - v00, v00);
            float bot = fmaf(wx, v11 - v10, v10);
            float cl_l = fmaf(wy, bot - top, top);

            float fy1 = fmaf(cl_l, 100.0f/(255.0f*116.0f), 16.0f/116.0f);
            float X = finv(fy1 + a500[k]);
            float Z = finv(fy1 + nb200[k]);
            float Y = finv(fy1);
            Ro[k] = srgb255s( 3.0799546f*X - 1.5371385f*Y - 0.5428164f*Z);
            Go[k] = srgb255s(-0.9212582f*X + 1.8760108f*Y + 0.0452474f*Z);
            Bo[k] = srgb255s( 0.0528874f*X - 0.2040259f*Y + 1.1511382f*Z);
        }
        __stcs((float4*)(out + base1),        *(float4*)Ro);
        __stcs((float4*)(out + base1 + HW),   *(float4*)Go);
        __stcs((float4*)(out + base1 + 2*HW), *(float4*)Bo);
    }
}

// ---------------- launch ----------------
extern "C" void kernel_launch(void* const* d_in, const int* in_sizes, int n_in,
                              void* d_out, int out_size) {
    const float* x = (const float*)d_in[0];
    float* out = (float*)d_out;
    (void)in_sizes; (void)n_in; (void)out_size;

    k_lab<<<LAB_BLOCKS8, 256>>>(x);
    k_quant_hist_lut<<<N_IMG * NTILES, 256>>>();
    k_luts2<<<N_IMG * QGRID * QGRID + N_IMG, NBINS>>>();
    k_out<<<OUT_BLOCKS, 256>>>(out);
}

// round 17
// speedup vs baseline: 1.0726x; 1.0246x over previous
#include <cuda_runtime.h>
#include <cuda_fp16.h>
#include <math.h>

#define N_IMG 16
#define HH 512
#define WW 512
#define HW (HH*WW)
#define NPIX (N_IMG*HW)
#define GRIDN 8
#define TH 64
#define TW 64
#define AREA (TH*TW)
#define NBINS 256
#define NTILES (GRIDN*GRIDN)
#define LAB_BLOCKS8 (NPIX/8/256)         // 2048 (k_lab, 8 px/thread)
#define LAB_BPI8 (LAB_BLOCKS8/N_IMG)     // 128
#define OUT_BLOCKS (NPIX/4/256)          // 4096 (k_out, 4 px/thread)
#define OUT_BPI (OUT_BLOCKS/N_IMG)       // 256
#define MINMAX_N LAB_BLOCKS8
#define QGRID 7
#define QPERIMG (QGRID*QGRID*NBINS)
#define QROWBLKS (N_IMG*QGRID)           // 112 quad-row blocks

#define LAB_EPS (216.0f/24389.0f)
#define LAB_KAPPA (24389.0f/27.0f)

// ---------------- scratch ----------------
__device__ float   g_L[NPIX];
__device__ __half2 g_ab[NPIX];           // pre-scaled (a/500, -b/200)
__device__ unsigned char g_lint[NPIX];
__device__ float g_blkmin[MINMAX_N];
__device__ float g_blkmax[MINMAX_N];
__device__ int    g_tilehist[N_IMG*NTILES*NBINS];
__device__ float  g_tilelut [N_IMG*NTILES*NBINS];
__device__ float2 g_eqlut2  [N_IMG*NBINS];      // (fy0, finv(fy0))
__device__ unsigned int g_quadU[N_IMG*QPERIMG]; // packed uchar corners
__device__ int4   g_cxlut4  [WW/4];             // per 4-px group: (wx0, x0*NBINS, dwx, 0)
__device__ int2   g_cylut   [HH];

// ---------------- MUFU primitives ----------------
__device__ __forceinline__ float ex2f(float x){ float r; asm("ex2.approx.f32 %0, %1;" : "=f"(r) : "f"(x)); return r; }
__device__ __forceinline__ float lg2f(float x){ float r; asm("lg2.approx.f32 %0, %1;" : "=f"(r) : "f"(x)); return r; }

// ---------------- scalar helpers ----------------
__device__ __forceinline__ float srgb2lin(float c) {
    float lin = c * (1.0f/12.92f);
    float p = ex2f(2.4f * lg2f(fmaf(c, 1.0f/1.055f, 0.055f/1.055f)));
    return (c <= 0.04045f) ? lin : p;
}
__device__ __forceinline__ float labf(float x) {
    float lin = fmaf(x, LAB_KAPPA/116.0f, 16.0f/116.0f);
    float p = ex2f(lg2f(x) * (1.0f/3.0f));
    return (x > LAB_EPS) ? p : lin;
}
__device__ __forceinline__ float finv(float f) {
    float f3 = f * f * f;
    float lin = fmaf(f, 116.0f/LAB_KAPPA, -16.0f/LAB_KAPPA);
    return (f3 > LAB_EPS) ? f3 : lin;
}
__device__ __forceinline__ float srgb255s(float c) {
    float lin = c * (12.92f * 255.0f);
    float p = ex2f(fmaf(lg2f(c), 1.0f/2.4f, 8.0715942f)) - 14.025f;
    float r = (c <= 0.0031308f) ? lin : p;
    return fminf(fmaxf(r, 0.0f), 255.0f);
}
// exact uchar->float via PRMT + magic subtract
__device__ __forceinline__ float ub2f(unsigned int q, int sel) {
    return __uint_as_float(__byte_perm(q, 0x4B000000u, sel)) - 8388608.0f;
}

__device__ __forceinline__ float inclusive_scan_256(float v, float* ws8) {
    int lane = threadIdx.x & 31, warp = threadIdx.x >> 5;
    #pragma unroll
    for (int o = 1; o < 32; o <<= 1) {
        float t = __shfl_up_sync(0xFFFFFFFFu, v, o);
        if (lane >= o) v += t;
    }
    if (lane == 31) ws8[warp] = v;
    __syncthreads();
    if (warp == 0 && lane < 8) {
        float s = ws8[lane];
        #pragma unroll
        for (int o = 1; o < 8; o <<= 1) {
            float t = __shfl_up_sync(0xFFu, s, o);
            if (lane >= o) s += t;
        }
        ws8[lane] = s;
    }
    __syncthreads();
    if (warp > 0) v += ws8[warp - 1];
    return v;
}

// ---------------- K1: RGB -> Lab (8 px/thread) + per-block min/max ----------------
__global__ void k_lab(const float* __restrict__ x) {
    int t  = blockIdx.x * blockDim.x + threadIdx.x;
    int p8 = t * 8;
    int n  = blockIdx.x / LAB_BPI8;
    int hw = p8 - n * HW;
    const float* img = x + (size_t)n * 3 * HW;
    float4 R0 = __ldcs((const float4*)(img + hw));
    float4 R1 = __ldcs((const float4*)(img + hw + 4));
    float4 G0 = __ldcs((const float4*)(img + HW + hw));
    float4 G1 = __ldcs((const float4*)(img + HW + hw + 4));
    float4 B0 = __ldcs((const float4*)(img + 2*HW + hw));
    float4 B1 = __ldcs((const float4*)(img + 2*HW + hw + 4));
    float Rf[8], Gf[8], Bf[8];
    *(float4*)(Rf) = R0; *(float4*)(Rf+4) = R1;
    *(float4*)(Gf) = G0; *(float4*)(Gf+4) = G1;
    *(float4*)(Bf) = B0; *(float4*)(Bf+4) = B1;

    float Lo[8];
    __half2 ab[8];
    float vmin =  1e30f, vmax = -1e30f;
    #pragma unroll
    for (int k = 0; k < 8; k++) {
        float lr = srgb2lin(Rf[k]);
        float lg = srgb2lin(Gf[k]);
        float lb = srgb2lin(Bf[k]);
        float X = 0.43395038f*lr;
        X = fmaf(0.37621015f, lg, X);
        X = fmaf(0.18984050f, lb, X);
        float Y = 0.21267290f*lr;
        Y = fmaf(0.71515220f, lg, Y);
        Y = fmaf(0.07217500f, lb, Y);
        float Z = 0.01775650f*lr;
        Z = fmaf(0.10946790f, lg, Z);
        Z = fmaf(0.87277544f, lb, Z);
        float fx = labf(X), fy = labf(Y), fz = labf(Z);
        float L = fmaf(fy, 116.0f, -16.0f);
        // pre-scaled chroma: a/500 = fx - fy ; -b/200 = fz - fy
        ab[k] = __floats2half2_rn(fx - fy, fz - fy);
        Lo[k] = L;
        vmin = fminf(vmin, L); vmax = fmaxf(vmax, L);
    }
    *(float4*)(g_L + p8)     = *(float4*)Lo;
    *(float4*)(g_L + p8 + 4) = *(float4*)(Lo + 4);
    *(uint4*)(g_ab + p8)     = *(uint4*)ab;
    *(uint4*)(g_ab + p8 + 4) = *(uint4*)(ab + 4);

    #pragma unroll
    for (int o = 16; o > 0; o >>= 1) {
        vmin = fminf(vmin, __shfl_down_sync(0xFFFFFFFFu, vmin, o));
        vmax = fmaxf(vmax, __shfl_down_sync(0xFFFFFFFFu, vmax, o));
    }
    __shared__ float wmin[8], wmax[8];
    int lane = threadIdx.x & 31, warp = threadIdx.x >> 5;
    if (lane == 0) { wmin[warp] = vmin; wmax[warp] = vmax; }
    __syncthreads();
    if (threadIdx.x == 0) {
        float bmin = wmin[0], bmax = wmax[0];
        #pragma unroll
        for (int i = 1; i < 8; i++) {
            bmin = fminf(bmin, wmin[i]);
            bmax = fmaxf(bmax, wmax[i]);
        }
        g_blkmin[blockIdx.x] = bmin;
        g_blkmax[blockIdx.x] = bmax;
    }
}

// ---------------- K2: min/max finalize + quantize + tile hist + tile LUT ----------------
__global__ void k_quant_hist_lut() {
    int blk = blockIdx.x;
    int n = blk >> 6;
    int t = blk & 63;
    int ty = t >> 3, tx = t & 7;

    __shared__ int shw[8][NBINS];
    __shared__ float wmin[8], wmax[8];
    __shared__ float ws8[8];
    __shared__ float s_lmin, s_scale, s_totc;

    float vmin =  1e30f, vmax = -1e30f;
    if (threadIdx.x < LAB_BPI8) {
        vmin = g_blkmin[n * LAB_BPI8 + threadIdx.x];
        vmax = g_blkmax[n * LAB_BPI8 + threadIdx.x];
    }
    #pragma unroll
    for (int o = 16; o > 0; o >>= 1) {
        vmin = fminf(vmin, __shfl_down_sync(0xFFFFFFFFu, vmin, o));
        vmax = fmaxf(vmax, __shfl_down_sync(0xFFFFFFFFu, vmax, o));
    }
    int lane = threadIdx.x & 31, warp = threadIdx.x >> 5;
    if (lane == 0) { wmin[warp] = vmin; wmax[warp] = vmax; }
    #pragma unroll
    for (int w = 0; w < 8; w++) shw[w][threadIdx.x] = 0;
    __syncthreads();
    if (threadIdx.x == 0) {
        float bmin = wmin[0], bmax = wmax[0];
        #pragma unroll
        for (int i = 1; i < 4; i++) {
            bmin = fminf(bmin, wmin[i]);
            bmax = fmaxf(bmax, wmax[i]);
        }
        s_lmin = bmin;
        s_scale = 255.0f / (bmax - bmin + 1e-6f);
    }
    __syncthreads();

    float lmin = s_lmin, scale = s_scale;
    int* myh = shw[warp];
    int base = n * HW + (ty * TH) * WW + tx * TW;
    #pragma unroll
    for (int it = 0; it < 4; it++) {
        int i = threadIdx.x + it * 256;
        int row = i >> 4, c16 = i & 15;
        int p = base + row * WW + c16 * 4;
        float4 L4 = __ldlu((const float4*)(g_L + p));
        int v0 = min(max((int)rintf((L4.x - lmin) * scale), 0), 255);
        int v1 = min(max((int)rintf((L4.y - lmin) * scale), 0), 255);
        int v2 = min(max((int)rintf((L4.z - lmin) * scale), 0), 255);
        int v3 = min(max((int)rintf((L4.w - lmin) * scale), 0), 255);
        *(uchar4*)(g_lint + p) = make_uchar4((unsigned char)v0, (unsigned char)v1,
                                             (unsigned char)v2, (unsigned char)v3);
        atomicAdd(&myh[v0], 1);
        atomicAdd(&myh[v1], 1);
        atomicAdd(&myh[v2], 1);
        atomicAdd(&myh[v3], 1);
    }
    __syncthreads();

    int hist = 0;
    #pragma unroll
    for (int w = 0; w < 8; w++) hist += shw[w][threadIdx.x];
    g_tilehist[blk * NBINS + threadIdx.x] = hist;

    float clipped = fminf((float)hist, 32.0f);
    float cum = inclusive_scan_256(clipped, ws8);
    if (threadIdx.x == 255) s_totc = cum;
    __syncthreads();
    float excess = (float)AREA - s_totc;
    float val = cum + (float)(threadIdx.x + 1) * (excess * (1.0f/256.0f));
    g_tilelut[blk * NBINS + threadIdx.x] = rintf(val * (255.0f / (float)AREA));
}

// ---------------- K3: quad table (row blocks) + equalize LUT + coord LUTs ----------------
// blocks [0, 112): one per (n, y0) — emits all 7 x0 quads for the row
// blocks [112, 128): eq LUT per image (+ coord LUTs on n=0/1)
__global__ void k_luts2() {
    int blk = blockIdx.x;
    int t = threadIdx.x;
    if (blk < QROWBLKS) {
        int n  = blk / QGRID;
        int y0 = blk - n * QGRID;
        const float* lb = g_tilelut + ((n * GRIDN + y0) * GRIDN) * NBINS + t;
        unsigned int top[8], bot[8];
        #pragma unroll
        for (int xx = 0; xx < 8; xx++) {
            top[xx] = (unsigned int)lb[xx * NBINS];
            bot[xx] = (unsigned int)lb[(GRIDN + xx) * NBINS];
        }
        unsigned int* qdst = g_quadU + (n * QGRID + y0) * (QGRID * NBINS) + t;
        #pragma unroll
        for (int x0 = 0; x0 < QGRID; x0++) {
            qdst[x0 * NBINS] = top[x0] | (top[x0+1] << 8)
                             | (bot[x0] << 16) | (bot[x0+1] << 24);
        }
    } else {
        __shared__ float ws8[8];
        int n = blk - QROWBLKS;
        int s = 0;
        #pragma unroll
        for (int tt = 0; tt < NTILES; tt++)
            s += g_tilehist[(n * NTILES + tt) * NBINS + t];
        float cum = inclusive_scan_256((float)s, ws8);
        float eq_l = rintf(cum * (255.0f / (float)HW));
        float fy0 = fmaf(eq_l, 100.0f/(255.0f*116.0f), 16.0f/116.0f);
        g_eqlut2[n * NBINS + t] = make_float2(fy0, finv(fy0));

        if (n == 0) {
            if (t < WW/4) {
                int w = t * 4;
                float cx0 = fminf(fmaxf(((float)w + 0.5f) * (1.0f/TW) - 0.5f, 0.0f), 7.0f);
                float cx1 = fminf(fmaxf(((float)w + 1.5f) * (1.0f/TW) - 0.5f, 0.0f), 7.0f);
                int x0 = min((int)cx0, GRIDN - 2);
                float wx0 = cx0 - (float)x0;
                float dwx = cx1 - cx0;            // exactly 0 or 1/64
                g_cxlut4[t] = make_int4(__float_as_int(wx0), x0 * NBINS,
                                        __float_as_int(dwx), 0);
            }
        } else if (n == 1) {
            #pragma unroll
            for (int h = t; h < HH; h += 256) {
                float cy = fminf(fmaxf(((float)h + 0.5f) * (1.0f/TH) - 0.5f, 0.0f), 7.0f);
                int y0 = min((int)cy, GRIDN - 2);
                g_cylut[h] = make_int2(__float_as_int(cy - (float)y0), y0 * (QGRID * NBINS));
            }
        }
    }
}

// ---------------- K4: reconstruct both outputs (4 px/thread, group-cx LUT) ----------
__global__ void __launch_bounds__(256, 6) k_out(float* __restrict__ out) {
    int t  = blockIdx.x * blockDim.x + threadIdx.x;
    int p4 = t * 4;
    int n  = blockIdx.x / OUT_BPI;
    int hw = p4 - n * HW;
    int h = hw >> 9, w0 = hw & 511;

    unsigned int lraw = __ldlu((const unsigned int*)(g_lint + p4));
    uchar4 v4 = *(uchar4*)&lraw;
    uint4 abraw = __ldlu((const uint4*)(g_ab + p4));

    const float2* eqn = g_eqlut2 + n * NBINS;

    float a500[4], nb200[4];
    #pragma unroll
    for (int k = 0; k < 4; k++) {
        unsigned int abu = (k==0)?abraw.x:(k==1)?abraw.y:(k==2)?abraw.z:abraw.w;
        float2 abf = __half22float2(*(__half2*)&abu);
        a500[k]  = abf.x;            // a/500 pre-scaled
        nb200[k] = abf.y;            // -b/200 pre-scaled
    }

    size_t base0 = (size_t)n * 3 * HW + hw;
    size_t base1 = (size_t)NPIX * 3 + base0;

    // ---- phase 1: equalize output ----
    {
        float Ro[4], Go[4], Bo[4];
        #pragma unroll
        for (int k = 0; k < 4; k++) {
            int v = (k==0)?v4.x:(k==1)?v4.y:(k==2)?v4.z:v4.w;
            float2 eqv = eqn[v];                  // (fy0, finv(fy0))
            float X = finv(eqv.x + a500[k]);
            float Z = finv(eqv.x + nb200[k]);
            float Y = eqv.y;
            Ro[k] = srgb255s( 3.0799546f*X - 1.5371385f*Y - 0.5428164f*Z);
            Go[k] = srgb255s(-0.9212582f*X + 1.8760108f*Y + 0.0452474f*Z);
            Bo[k] = srgb255s( 0.0528874f*X - 0.2040259f*Y + 1.1511382f*Z);
        }
        __stcs((float4*)(out + base0),        *(float4*)Ro);
        __stcs((float4*)(out + base0 + HW),   *(float4*)Go);
        __stcs((float4*)(out + base0 + 2*HW), *(float4*)Bo);
    }

    // ---- phase 2: clahe output ----
    {
        int2 cye = g_cylut[h];
        float wy = __int_as_float(cye.x);
        int4 cxe = g_cxlut4[w0 >> 2];             // one load per 4-px group
        float wx0 = __int_as_float(cxe.x);
        float dwx = __int_as_float(cxe.z);
        const unsigned int* qrow = g_quadU + n * QPERIMG + cye.y + cxe.y;

        float Ro[4], Go[4], Bo[4];
        #pragma unroll
        for (int k = 0; k < 4; k++) {
            int v = (k==0)?v4.x:(k==1)?v4.y:(k==2)?v4.z:v4.w;
            float wx = fmaf((float)k, dwx, wx0);
            unsigned int q = qrow[v];
            float v00 = ub2f(q, 0x7440);
            float v01 = ub2f(q, 0x7441);
            float v10 = ub2f(q, 0x7442);
            float v11 = ub2f(q, 0x7443);
            float top = fmaf(wx, v01 - v00, v00);
            float bot = fmaf(wx, v11 - v10, v10);
            float cl_l = fmaf(wy, bot - top, top);

            float fy1 = fmaf(cl_l, 100.0f/(255.0f*116.0f), 16.0f/116.0f);
            float X = finv(fy1 + a500[k]);
            float Z = finv(fy1 + nb200[k]);
            float Y = finv(fy1);
            Ro[k] = srgb255s( 3.0799546f*X - 1.5371385f*Y - 0.5428164f*Z);
            Go[k] = srgb255s(-0.9212582f*X + 1.8760108f*Y + 0.0452474f*Z);
            Bo[k] = srgb255s( 0.0528874f*X - 0.2040259f*Y + 1.1511382f*Z);
        }
        __stcs((float4*)(out + base1),        *(float4*)Ro);
        __stcs((float4*)(out + base1 + HW),   *(float4*)Go);
        __stcs((float4*)(out + base1 + 2*HW), *(float4*)Bo);
    }
}

// ---------------- launch ----------------
extern "C" void kernel_launch(void* const* d_in, const int* in_sizes, int n_in,
                              void* d_out, int out_size) {
    const float* x = (const float*)d_in[0];
    float* out = (float*)d_out;
    (void)in_sizes; (void)n_in; (void)out_size;

    k_lab<<<LAB_BLOCKS8, 256>>>(x);
    k_quant_hist_lut<<<N_IMG * NTILES, 256>>>();
    k_luts2<<<QROWBLKS + N_IMG, NBINS>>>();
    k_out<<<OUT_BLOCKS, 256>>>(out);
}